// round 1
// baseline (speedup 1.0000x reference)
#include <cuda_runtime.h>
#include <cuda_bf16.h>
#include <math_constants.h>
#include <cstdint>

// ---------------- problem constants ----------------
#define NMAX     8000
#define EMAX     256000
#define C_IN     16
#define H_IN     30
#define C_HID    16
#define C_OUT    32
#define FLAT     1568      // 32*7*7
#define MLP_HID  512
#define MLP_OUT  256
#define GNN_HID  256
#define EMB      128
#define HEADS    2

// ---------------- scratch (static device globals; no allocation) ------------
__device__ float g_pool1[(size_t)NMAX * C_HID * 15 * 15];   // after conv1+pool
__device__ float g_pool2[(size_t)NMAX * FLAT];              // after conv2+pool (flat)
__device__ float g_feat1[(size_t)NMAX * MLP_HID];
__device__ float g_feat2[(size_t)NMAX * MLP_OUT];
__device__ float g_h1   [(size_t)NMAX * HEADS * GNN_HID];
__device__ float g_h2   [(size_t)NMAX * HEADS * EMB];
__device__ float g_out1 [(size_t)NMAX * GNN_HID];
__device__ float g_als  [(size_t)NMAX * HEADS];
__device__ float g_ald  [(size_t)NMAX * HEADS];
__device__ int   g_cnt  [NMAX];
__device__ int   g_fill [NMAX];
__device__ int   g_rowptr[NMAX + 1];
__device__ int   g_srcs [EMAX];

// ---------------- CSR build ----------------
__global__ void hist_kernel(const int* __restrict__ ei, int* __restrict__ cnt, int E) {
    int e = blockIdx.x * blockDim.x + threadIdx.x;
    if (e < E) atomicAdd(&cnt[ei[E + e]], 1);
}

__global__ void scan_kernel(const int* __restrict__ cnt, int* __restrict__ rowptr,
                            int n, int total) {
    __shared__ int part[1024];
    const int PER = 8;                       // 1024*8 = 8192 >= n
    int tid = threadIdx.x;
    int base = tid * PER;
    int local[PER];
    int s = 0;
#pragma unroll
    for (int i = 0; i < PER; i++) {
        int v = (base + i < n) ? cnt[base + i] : 0;
        local[i] = v; s += v;
    }
    part[tid] = s;
    __syncthreads();
    for (int off = 1; off < 1024; off <<= 1) {
        int v = (tid >= off) ? part[tid - off] : 0;
        __syncthreads();
        part[tid] += v;
        __syncthreads();
    }
    int excl = part[tid] - s;
#pragma unroll
    for (int i = 0; i < PER; i++) {
        if (base + i < n) { rowptr[base + i] = excl; excl += local[i]; }
    }
    if (tid == 0) rowptr[n] = total;
}

__global__ void scatter_kernel(const int* __restrict__ ei, const int* __restrict__ rowptr,
                               int* __restrict__ fill, int* __restrict__ srcs, int E) {
    int e = blockIdx.x * blockDim.x + threadIdx.x;
    if (e >= E) return;
    int s = ei[e];
    int d = ei[E + e];
    int pos = rowptr[d] + atomicAdd(&fill[d], 1);
    srcs[pos] = s;
}

// ---------------- conv1: 16ch 30x30 -> conv3x3 pad1 + relu + maxpool2 -> 16ch 15x15
__global__ void conv1_kernel(const float* __restrict__ states,
                             const float* __restrict__ w,
                             const float* __restrict__ b,
                             float* __restrict__ out) {
    extern __shared__ float sm[];
    float* s_in = sm;                 // 16*900 = 14400
    float* s_w  = sm + 14400;         // 16*16*9 = 2304
    float* s_b  = s_w + 2304;         // 16
    const int n = blockIdx.x;
    const int tid = threadIdx.x;
    const float* img = states + (size_t)n * 14400;
    for (int i = tid; i < 14400; i += 256) s_in[i] = img[i];
    for (int i = tid; i < 2304; i += 256) s_w[i] = w[i];
    if (tid < 16) s_b[tid] = b[tid];
    __syncthreads();

    const int co = tid >> 4;          // 0..15
    const int lane = tid & 15;
    float* outp = out + (size_t)n * (16 * 225) + co * 225;
    const float* wco = s_w + co * 144;
    const float bias = s_b[co];

    for (int p = lane; p < 225; p += 16) {
        int ph = p / 15, pw = p % 15;
        int ry0 = 2 * ph - 1, rx0 = 2 * pw - 1;
        float a00 = bias, a01 = bias, a10 = bias, a11 = bias;
        for (int ci = 0; ci < 16; ci++) {
            const float* ip = s_in + ci * 900;
            const float* wp = wco + ci * 9;
            float patch[4][4];
#pragma unroll
            for (int i = 0; i < 4; i++) {
                int y = ry0 + i;
                bool yv = (y >= 0) && (y < 30);
#pragma unroll
                for (int j = 0; j < 4; j++) {
                    int x = rx0 + j;
                    patch[i][j] = (yv && x >= 0 && x < 30) ? ip[y * 30 + x] : 0.f;
                }
            }
            float wv[9];
#pragma unroll
            for (int k = 0; k < 9; k++) wv[k] = wp[k];
#pragma unroll
            for (int kh = 0; kh < 3; kh++) {
#pragma unroll
                for (int kw = 0; kw < 3; kw++) {
                    float wk = wv[kh * 3 + kw];
                    a00 += patch[kh][kw] * wk;
                    a01 += patch[kh][kw + 1] * wk;
                    a10 += patch[kh + 1][kw] * wk;
                    a11 += patch[kh + 1][kw + 1] * wk;
                }
            }
        }
        float m = fmaxf(fmaxf(a00, a01), fmaxf(a10, a11));
        outp[p] = fmaxf(m, 0.f);
    }
}

// ---------------- conv2: 16ch 15x15 -> conv3x3 pad1 + relu + pool2 -> 32ch 7x7
__global__ void conv2_kernel(const float* __restrict__ in,
                             const float* __restrict__ w,
                             const float* __restrict__ b,
                             float* __restrict__ out) {
    __shared__ float s_in[16 * 225];
    __shared__ float s_w[32 * 16 * 9];
    __shared__ float s_b[32];
    const int n = blockIdx.x;
    const int tid = threadIdx.x;
    const float* img = in + (size_t)n * 3600;
    for (int i = tid; i < 3600; i += 256) s_in[i] = img[i];
    for (int i = tid; i < 4608; i += 256) s_w[i] = w[i];
    if (tid < 32) s_b[tid] = b[tid];
    __syncthreads();

    const int co = tid >> 3;          // 0..31
    const int lane = tid & 7;
    float* outp = out + (size_t)n * FLAT + co * 49;
    const float* wco = s_w + co * 144;
    const float bias = s_b[co];

    for (int p = lane; p < 49; p += 8) {
        int ph = p / 7, pw = p % 7;
        int ry0 = 2 * ph - 1, rx0 = 2 * pw - 1;
        float a00 = bias, a01 = bias, a10 = bias, a11 = bias;
        for (int ci = 0; ci < 16; ci++) {
            const float* ip = s_in + ci * 225;
            const float* wp = wco + ci * 9;
            float patch[4][4];
#pragma unroll
            for (int i = 0; i < 4; i++) {
                int y = ry0 + i;
                bool yv = (y >= 0) && (y < 15);
#pragma unroll
                for (int j = 0; j < 4; j++) {
                    int x = rx0 + j;
                    patch[i][j] = (yv && x >= 0 && x < 15) ? ip[y * 15 + x] : 0.f;
                }
            }
            float wv[9];
#pragma unroll
            for (int k = 0; k < 9; k++) wv[k] = wp[k];
#pragma unroll
            for (int kh = 0; kh < 3; kh++) {
#pragma unroll
                for (int kw = 0; kw < 3; kw++) {
                    float wk = wv[kh * 3 + kw];
                    a00 += patch[kh][kw] * wk;
                    a01 += patch[kh][kw + 1] * wk;
                    a10 += patch[kh + 1][kw] * wk;
                    a11 += patch[kh + 1][kw + 1] * wk;
                }
            }
        }
        float m = fmaxf(fmaxf(a00, a01), fmaxf(a10, a11));
        outp[p] = fmaxf(m, 0.f);
    }
}

// ---------------- tiled SGEMM: C[M,N] = act(actIn(A[M,K]) @ B[K,N] + bias)
// Requirements (all satisfied by call sites): K % 16 == 0, N % 64 == 0.
#define BM 128
#define BN 64
#define BK 16
#define TM 8
#define TN 4

template <bool RELU_IN, bool RELU_OUT>
__global__ void __launch_bounds__(256)
sgemm_kernel(const float* __restrict__ A, const float* __restrict__ B,
             const float* __restrict__ bias, float* __restrict__ C,
             int M, int N, int K) {
    __shared__ float As[BK][BM + 4];
    __shared__ float Bs[BK][BN];
    const int tid = threadIdx.x;
    const int block_m = blockIdx.y * BM;
    const int block_n = blockIdx.x * BN;

    const int a_r  = tid >> 2;          // 0..63
    const int a_c4 = (tid & 3) * 4;     // 0,4,8,12
    const int b_r  = tid >> 4;          // 0..15
    const int b_c4 = (tid & 15) * 4;

    const int tx = tid & 15;            // N dir
    const int ty = tid >> 4;            // M dir

    float acc[TM][TN];
#pragma unroll
    for (int i = 0; i < TM; i++)
#pragma unroll
        for (int j = 0; j < TN; j++) acc[i][j] = 0.f;

    for (int k0 = 0; k0 < K; k0 += BK) {
#pragma unroll
        for (int rr = 0; rr < 2; rr++) {
            int row = block_m + a_r + rr * 64;
            float4 v = make_float4(0.f, 0.f, 0.f, 0.f);
            if (row < M) v = *(const float4*)(A + (size_t)row * K + k0 + a_c4);
            if (RELU_IN) {
                v.x = fmaxf(v.x, 0.f); v.y = fmaxf(v.y, 0.f);
                v.z = fmaxf(v.z, 0.f); v.w = fmaxf(v.w, 0.f);
            }
            As[a_c4 + 0][a_r + rr * 64] = v.x;
            As[a_c4 + 1][a_r + rr * 64] = v.y;
            As[a_c4 + 2][a_r + rr * 64] = v.z;
            As[a_c4 + 3][a_r + rr * 64] = v.w;
        }
        {
            float4 v = *(const float4*)(B + (size_t)(k0 + b_r) * N + block_n + b_c4);
            *(float4*)&Bs[b_r][b_c4] = v;
        }
        __syncthreads();
#pragma unroll
        for (int k = 0; k < BK; k++) {
            float a[TM];
#pragma unroll
            for (int i = 0; i < TM; i++) a[i] = As[k][ty * TM + i];
            float4 bv = *(float4*)&Bs[k][tx * TN];
            float bfr[TN] = {bv.x, bv.y, bv.z, bv.w};
#pragma unroll
            for (int i = 0; i < TM; i++)
#pragma unroll
                for (int j = 0; j < TN; j++) acc[i][j] += a[i] * bfr[j];
        }
        __syncthreads();
    }

#pragma unroll
    for (int i = 0; i < TM; i++) {
        int row = block_m + ty * TM + i;
        if (row >= M) continue;
#pragma unroll
        for (int j = 0; j < TN; j++) {
            int col = block_n + tx * TN + j;
            float v = acc[i][j] + (bias ? bias[col] : 0.f);
            if (RELU_OUT) v = fmaxf(v, 0.f);
            C[(size_t)row * N + col] = v;
        }
    }
}

// ---------------- GAT attention-coefficient prep: al_s/al_d[n,h] = <h[n,h,:], a>
template <int D>
__global__ void alpha_prep_kernel(const float* __restrict__ h,
                                  const float* __restrict__ a_src,
                                  const float* __restrict__ a_dst,
                                  float* __restrict__ als, float* __restrict__ ald,
                                  int N) {
    int w = (blockIdx.x * blockDim.x + threadIdx.x) >> 5;
    int lane = threadIdx.x & 31;
    if (w >= N * HEADS) return;
    int n = w >> 1, hd = w & 1;
    const float* hr = h + (size_t)n * (HEADS * D) + hd * D;
    const float* as = a_src + hd * D;
    const float* ad = a_dst + hd * D;
    float ss = 0.f, dd = 0.f;
    for (int i = lane; i < D; i += 32) {
        float v = hr[i];
        ss += v * as[i];
        dd += v * ad[i];
    }
#pragma unroll
    for (int o = 16; o; o >>= 1) {
        ss += __shfl_xor_sync(0xffffffffu, ss, o);
        dd += __shfl_xor_sync(0xffffffffu, dd, o);
    }
    if (lane == 0) {
        als[n * HEADS + hd] = ss;
        ald[n * HEADS + hd] = dd;
    }
}

// ---------------- fused per-node GAT: softmax over in-edges + weighted agg + head-mean + bias
#define GCHUNK 64

template <int D>
__global__ void gat_node_kernel(const float* __restrict__ h,
                                const float* __restrict__ als,
                                const float* __restrict__ ald,
                                const float* __restrict__ bias,
                                const int* __restrict__ rowptr,
                                const int* __restrict__ srcs,
                                float* __restrict__ out) {
    constexpr int NW = D / 32;
    const int n = blockIdx.x;
    const int tid = threadIdx.x;     // blockDim == D
    const int beg = rowptr[n];
    const int deg = rowptr[n + 1] - beg;

    if (deg == 0) {
        out[(size_t)n * D + tid] = bias[tid];
        return;
    }

    __shared__ float rbuf[NW];
    __shared__ float bc;
    __shared__ int   src_sm[GCHUNK];
    __shared__ float a0_sm[GCHUNK];
    __shared__ float a1_sm[GCHUNK];

    const float ad0 = ald[n * 2 + 0];
    const float ad1 = ald[n * 2 + 1];

    auto edge_e = [&](int s, float& e0, float& e1) {
        e0 = als[s * 2 + 0] + ad0;
        e0 = (e0 > 0.f) ? e0 : 0.2f * e0;
        e1 = als[s * 2 + 1] + ad1;
        e1 = (e1 > 0.f) ? e1 : 0.2f * e1;
    };

    auto block_max = [&](float v) -> float {
#pragma unroll
        for (int o = 16; o; o >>= 1) v = fmaxf(v, __shfl_xor_sync(0xffffffffu, v, o));
        if ((tid & 31) == 0) rbuf[tid >> 5] = v;
        __syncthreads();
        if (tid == 0) {
            float r = rbuf[0];
#pragma unroll
            for (int i = 1; i < NW; i++) r = fmaxf(r, rbuf[i]);
            bc = r;
        }
        __syncthreads();
        float r = bc;
        __syncthreads();
        return r;
    };
    auto block_sum = [&](float v) -> float {
#pragma unroll
        for (int o = 16; o; o >>= 1) v += __shfl_xor_sync(0xffffffffu, v, o);
        if ((tid & 31) == 0) rbuf[tid >> 5] = v;
        __syncthreads();
        if (tid == 0) {
            float r = 0.f;
#pragma unroll
            for (int i = 0; i < NW; i++) r += rbuf[i];
            bc = r;
        }
        __syncthreads();
        float r = bc;
        __syncthreads();
        return r;
    };

    // phase A: per-head max
    float m0 = -CUDART_INF_F, m1 = -CUDART_INF_F;
    for (int j = tid; j < deg; j += D) {
        float e0, e1;
        edge_e(srcs[beg + j], e0, e1);
        m0 = fmaxf(m0, e0);
        m1 = fmaxf(m1, e1);
    }
    m0 = block_max(m0);
    m1 = block_max(m1);

    // phase B: per-head sum of exp
    float s0 = 0.f, s1 = 0.f;
    for (int j = tid; j < deg; j += D) {
        float e0, e1;
        edge_e(srcs[beg + j], e0, e1);
        s0 += __expf(e0 - m0);
        s1 += __expf(e1 - m1);
    }
    s0 = block_sum(s0);
    s1 = block_sum(s1);
    const float inv0 = 1.0f / (s0 + 1e-16f);
    const float inv1 = 1.0f / (s1 + 1e-16f);

    // phase C: chunked alpha + weighted accumulation
    float acc0 = 0.f, acc1 = 0.f;
    for (int base = 0; base < deg; base += GCHUNK) {
        int cnt = min(GCHUNK, deg - base);
        if (tid < cnt) {
            int s = srcs[beg + base + tid];
            float e0, e1;
            edge_e(s, e0, e1);
            src_sm[tid] = s;
            a0_sm[tid] = __expf(e0 - m0) * inv0;
            a1_sm[tid] = __expf(e1 - m1) * inv1;
        }
        __syncthreads();
        for (int j = 0; j < cnt; j++) {
            const float* hr = h + (size_t)src_sm[j] * (2 * D);
            acc0 += a0_sm[j] * hr[tid];
            acc1 += a1_sm[j] * hr[D + tid];
        }
        __syncthreads();
    }
    out[(size_t)n * D + tid] = 0.5f * (acc0 + acc1) + bias[tid];
}

// ---------------- launch ----------------
extern "C" void kernel_launch(void* const* d_in, const int* in_sizes, int n_in,
                              void* d_out, int out_size) {
    const float* states = (const float*)d_in[0];
    const int*   ei     = (const int*)d_in[1];
    const float* c1w = (const float*)d_in[2];
    const float* c1b = (const float*)d_in[3];
    const float* c2w = (const float*)d_in[4];
    const float* c2b = (const float*)d_in[5];
    const float* m1w = (const float*)d_in[6];
    const float* m1b = (const float*)d_in[7];
    const float* m2w = (const float*)d_in[8];
    const float* m2b = (const float*)d_in[9];
    const float* g1W  = (const float*)d_in[10];
    const float* g1as = (const float*)d_in[11];
    const float* g1ad = (const float*)d_in[12];
    const float* g1b  = (const float*)d_in[13];
    const float* g2W  = (const float*)d_in[14];
    const float* g2as = (const float*)d_in[15];
    const float* g2ad = (const float*)d_in[16];
    const float* g2b  = (const float*)d_in[17];
    float* out = (float*)d_out;

    const int Nn = in_sizes[0] / (C_IN * H_IN * H_IN);
    const int Ee = in_sizes[1] / 2;

    // device pointers for scratch
    float *p_pool1, *p_pool2, *p_feat1, *p_feat2, *p_h1, *p_h2, *p_out1, *p_als, *p_ald;
    int *p_cnt, *p_fill, *p_rowptr, *p_srcs;
    cudaGetSymbolAddress((void**)&p_pool1, g_pool1);
    cudaGetSymbolAddress((void**)&p_pool2, g_pool2);
    cudaGetSymbolAddress((void**)&p_feat1, g_feat1);
    cudaGetSymbolAddress((void**)&p_feat2, g_feat2);
    cudaGetSymbolAddress((void**)&p_h1, g_h1);
    cudaGetSymbolAddress((void**)&p_h2, g_h2);
    cudaGetSymbolAddress((void**)&p_out1, g_out1);
    cudaGetSymbolAddress((void**)&p_als, g_als);
    cudaGetSymbolAddress((void**)&p_ald, g_ald);
    cudaGetSymbolAddress((void**)&p_cnt, g_cnt);
    cudaGetSymbolAddress((void**)&p_fill, g_fill);
    cudaGetSymbolAddress((void**)&p_rowptr, g_rowptr);
    cudaGetSymbolAddress((void**)&p_srcs, g_srcs);

    cudaFuncSetAttribute(conv1_kernel, cudaFuncAttributeMaxDynamicSharedMemorySize,
                         (14400 + 2304 + 16) * (int)sizeof(float));

    // ---- CSR build (deterministic per launch) ----
    cudaMemsetAsync(p_cnt, 0, Nn * sizeof(int));
    cudaMemsetAsync(p_fill, 0, Nn * sizeof(int));
    hist_kernel<<<(Ee + 255) / 256, 256>>>(ei, p_cnt, Ee);
    scan_kernel<<<1, 1024>>>(p_cnt, p_rowptr, Nn, Ee);
    scatter_kernel<<<(Ee + 255) / 256, 256>>>(ei, p_rowptr, p_fill, p_srcs, Ee);

    // ---- CNN ----
    conv1_kernel<<<Nn, 256, (14400 + 2304 + 16) * sizeof(float)>>>(states, c1w, c1b, p_pool1);
    conv2_kernel<<<Nn, 256>>>(p_pool1, c2w, c2b, p_pool2);

    // ---- MLP ----
    dim3 gm1(MLP_HID / BN, (Nn + BM - 1) / BM);
    sgemm_kernel<false, true><<<gm1, 256>>>(p_pool2, m1w, m1b, p_feat1, Nn, MLP_HID, FLAT);
    dim3 gm2(MLP_OUT / BN, (Nn + BM - 1) / BM);
    sgemm_kernel<false, false><<<gm2, 256>>>(p_feat1, m2w, m2b, p_feat2, Nn, MLP_OUT, MLP_HID);

    // ---- GAT layer 1 ----
    dim3 gg1((HEADS * GNN_HID) / BN, (Nn + BM - 1) / BM);
    sgemm_kernel<false, false><<<gg1, 256>>>(p_feat2, g1W, nullptr, p_h1,
                                             Nn, HEADS * GNN_HID, MLP_OUT);
    alpha_prep_kernel<GNN_HID><<<(Nn * HEADS * 32 + 255) / 256, 256>>>(
        p_h1, g1as, g1ad, p_als, p_ald, Nn);
    gat_node_kernel<GNN_HID><<<Nn, GNN_HID>>>(p_h1, p_als, p_ald, g1b,
                                              p_rowptr, p_srcs, p_out1);

    // ---- GAT layer 2 (input relu fused into GEMM A-read) ----
    dim3 gg2((HEADS * EMB) / BN, (Nn + BM - 1) / BM);
    sgemm_kernel<true, false><<<gg2, 256>>>(p_out1, g2W, nullptr, p_h2,
                                            Nn, HEADS * EMB, GNN_HID);
    alpha_prep_kernel<EMB><<<(Nn * HEADS * 32 + 255) / 256, 256>>>(
        p_h2, g2as, g2ad, p_als, p_ald, Nn);
    gat_node_kernel<EMB><<<Nn, EMB>>>(p_h2, p_als, p_ald, g2b,
                                      p_rowptr, p_srcs, out);
}

// round 4
// speedup vs baseline: 1.4450x; 1.4450x over previous
#include <cuda_runtime.h>
#include <cuda_bf16.h>
#include <math_constants.h>
#include <cstdint>

// ---------------- problem constants ----------------
#define NMAX     8000
#define EMAX     256000
#define C_IN     16
#define H_IN     30
#define C_HID    16
#define C_OUT    32
#define FLAT     1568      // 32*7*7
#define MLP_HID  512
#define MLP_OUT  256
#define GNN_HID  256
#define EMB      128
#define HEADS    2

// ---------------- scratch (static device globals; no allocation) ------------
__device__ float g_pool1[(size_t)NMAX * C_HID * 15 * 15];   // after conv1+pool
__device__ float g_pool2[(size_t)NMAX * FLAT];              // after conv2+pool (flat)
__device__ float g_feat1[(size_t)NMAX * MLP_HID];
__device__ float g_feat2[(size_t)NMAX * MLP_OUT];
__device__ float g_h1   [(size_t)NMAX * HEADS * GNN_HID];
__device__ float g_h2   [(size_t)NMAX * HEADS * EMB];
__device__ float g_out1 [(size_t)NMAX * GNN_HID];
__device__ float g_als  [(size_t)NMAX * HEADS];
__device__ float g_ald  [(size_t)NMAX * HEADS];
__device__ int   g_cnt  [NMAX];
__device__ int   g_fill [NMAX];
__device__ int   g_rowptr[NMAX + 1];
__device__ int   g_srcs [EMAX];

// ---------------- CSR build ----------------
__global__ void hist_kernel(const int* __restrict__ ei, int* __restrict__ cnt, int E) {
    int e = blockIdx.x * blockDim.x + threadIdx.x;
    if (e < E) atomicAdd(&cnt[ei[E + e]], 1);
}

__global__ void scan_kernel(const int* __restrict__ cnt, int* __restrict__ rowptr,
                            int n, int total) {
    __shared__ int part[1024];
    const int PER = 8;                       // 1024*8 = 8192 >= n
    int tid = threadIdx.x;
    int base = tid * PER;
    int local[PER];
    int s = 0;
#pragma unroll
    for (int i = 0; i < PER; i++) {
        int v = (base + i < n) ? cnt[base + i] : 0;
        local[i] = v; s += v;
    }
    part[tid] = s;
    __syncthreads();
    for (int off = 1; off < 1024; off <<= 1) {
        int v = (tid >= off) ? part[tid - off] : 0;
        __syncthreads();
        part[tid] += v;
        __syncthreads();
    }
    int excl = part[tid] - s;
#pragma unroll
    for (int i = 0; i < PER; i++) {
        if (base + i < n) { rowptr[base + i] = excl; excl += local[i]; }
    }
    if (tid == 0) rowptr[n] = total;
}

__global__ void scatter_kernel(const int* __restrict__ ei, const int* __restrict__ rowptr,
                               int* __restrict__ fill, int* __restrict__ srcs, int E) {
    int e = blockIdx.x * blockDim.x + threadIdx.x;
    if (e >= E) return;
    int s = ei[e];
    int d = ei[E + e];
    int pos = rowptr[d] + atomicAdd(&fill[d], 1);
    srcs[pos] = s;
}

// ---------------- conv1: 16ch 30x30 -> conv3x3 pad1 + relu + maxpool2 -> 16ch 15x15
// 512 threads: thread = (co-group of 8, pooled position); 450 active.
// Weights padded to 12 floats per (co,ci) for float4 loads.
#define C1_SMEM_FLOATS (14400 + 16 * 16 * 12 + 16)

__global__ void __launch_bounds__(512)
conv1_kernel(const float* __restrict__ states,
             const float* __restrict__ w,
             const float* __restrict__ b,
             float* __restrict__ out) {
    extern __shared__ float sm[];
    float* s_in = sm;                       // 16*900 = 14400
    float* s_w  = sm + 14400;               // 16co*16ci*12 = 3072 (padded)
    float* s_b  = s_w + 16 * 16 * 12;       // 16
    const int n = blockIdx.x;
    const int tid = threadIdx.x;
    const float* img = states + (size_t)n * 14400;
    for (int i = tid; i < 14400; i += 512) s_in[i] = img[i];
    for (int i = tid; i < 16 * 16 * 9; i += 512) {
        int co = i / 144, r = i % 144, ci = r / 9, k = r % 9;
        s_w[co * 192 + ci * 12 + k] = w[i];
    }
    if (tid < 16) s_b[tid] = b[tid];
    __syncthreads();

    if (tid >= 450) return;
    const int cg = tid / 225;              // 0..1
    const int p = tid % 225;
    const int co0 = cg * 8;
    const int ph = p / 15, pw = p % 15;
    const int ry0 = 2 * ph - 1, rx0 = 2 * pw - 1;

    float acc[8][4];
#pragma unroll
    for (int c = 0; c < 8; c++) {
        float bb = s_b[co0 + c];
        acc[c][0] = bb; acc[c][1] = bb; acc[c][2] = bb; acc[c][3] = bb;
    }

    for (int ci = 0; ci < 16; ci++) {
        const float* ip = s_in + ci * 900;
        float patch[4][4];
#pragma unroll
        for (int i = 0; i < 4; i++) {
            int y = ry0 + i;
            bool yv = (y >= 0) && (y < 30);
#pragma unroll
            for (int j = 0; j < 4; j++) {
                int x = rx0 + j;
                patch[i][j] = (yv && x >= 0 && x < 30) ? ip[y * 30 + x] : 0.f;
            }
        }
        const float4* wp = (const float4*)(s_w + (size_t)co0 * 192 + ci * 12);
#pragma unroll
        for (int c = 0; c < 8; c++) {
            float4 w0 = wp[c * 48 + 0];
            float4 w1 = wp[c * 48 + 1];
            float4 w2 = wp[c * 48 + 2];
            float wv[9] = {w0.x, w0.y, w0.z, w0.w, w1.x, w1.y, w1.z, w1.w, w2.x};
#pragma unroll
            for (int kh = 0; kh < 3; kh++) {
#pragma unroll
                for (int kw = 0; kw < 3; kw++) {
                    float wk = wv[kh * 3 + kw];
                    acc[c][0] += patch[kh][kw] * wk;
                    acc[c][1] += patch[kh][kw + 1] * wk;
                    acc[c][2] += patch[kh + 1][kw] * wk;
                    acc[c][3] += patch[kh + 1][kw + 1] * wk;
                }
            }
        }
    }

    float* outp = out + (size_t)n * (16 * 225);
#pragma unroll
    for (int c = 0; c < 8; c++) {
        float m = fmaxf(fmaxf(acc[c][0], acc[c][1]), fmaxf(acc[c][2], acc[c][3]));
        outp[(co0 + c) * 225 + p] = fmaxf(m, 0.f);
    }
}

// ---------------- conv2: 16ch 15x15 -> conv3x3 pad1 + relu + pool2 -> 32ch 7x7
// Thread = (co-group of 8, pooled position). 196 active threads of 256.
__global__ void __launch_bounds__(256)
conv2_kernel(const float* __restrict__ in,
             const float* __restrict__ w,
             const float* __restrict__ b,
             float* __restrict__ out) {
    __shared__ float s_in[16 * 225];
    __shared__ float s_w[32 * 16 * 12];    // padded to 12
    __shared__ float s_b[32];
    const int n = blockIdx.x;
    const int tid = threadIdx.x;
    const float* img = in + (size_t)n * 3600;
    for (int i = tid; i < 3600; i += 256) s_in[i] = img[i];
    for (int i = tid; i < 32 * 16 * 9; i += 256) {
        int co = i / 144, r = i % 144, ci = r / 9, k = r % 9;
        s_w[co * 192 + ci * 12 + k] = w[i];
    }
    if (tid < 32) s_b[tid] = b[tid];
    __syncthreads();

    if (tid >= 196) return;
    const int cg = tid / 49;               // 0..3
    const int p = tid % 49;
    const int co0 = cg * 8;
    const int ph = p / 7, pw = p % 7;
    const int ry0 = 2 * ph - 1, rx0 = 2 * pw - 1;

    float acc[8][4];
#pragma unroll
    for (int c = 0; c < 8; c++) {
        float bb = s_b[co0 + c];
        acc[c][0] = bb; acc[c][1] = bb; acc[c][2] = bb; acc[c][3] = bb;
    }

    for (int ci = 0; ci < 16; ci++) {
        const float* ip = s_in + ci * 225;
        float patch[4][4];
#pragma unroll
        for (int i = 0; i < 4; i++) {
            int y = ry0 + i;
            bool yv = (y >= 0) && (y < 15);
#pragma unroll
            for (int j = 0; j < 4; j++) {
                int x = rx0 + j;
                patch[i][j] = (yv && x >= 0 && x < 15) ? ip[y * 15 + x] : 0.f;
            }
        }
        const float4* wp = (const float4*)(s_w + (size_t)co0 * 192 + ci * 12);
#pragma unroll
        for (int c = 0; c < 8; c++) {
            float4 w0 = wp[c * 48 + 0];
            float4 w1 = wp[c * 48 + 1];
            float4 w2 = wp[c * 48 + 2];
            float wv[9] = {w0.x, w0.y, w0.z, w0.w, w1.x, w1.y, w1.z, w1.w, w2.x};
#pragma unroll
            for (int kh = 0; kh < 3; kh++) {
#pragma unroll
                for (int kw = 0; kw < 3; kw++) {
                    float wk = wv[kh * 3 + kw];
                    acc[c][0] += patch[kh][kw] * wk;
                    acc[c][1] += patch[kh][kw + 1] * wk;
                    acc[c][2] += patch[kh + 1][kw] * wk;
                    acc[c][3] += patch[kh + 1][kw + 1] * wk;
                }
            }
        }
    }

    float* outp = out + (size_t)n * FLAT;
#pragma unroll
    for (int c = 0; c < 8; c++) {
        float m = fmaxf(fmaxf(acc[c][0], acc[c][1]), fmaxf(acc[c][2], acc[c][3]));
        outp[(co0 + c) * 49 + p] = fmaxf(m, 0.f);
    }
}

// ---------------- tiled SGEMM: C[M,N] = act(actIn(A[M,K]) @ B[K,N] + bias)
// BM=128, BN=128, BK=16, 256 threads, 8x8 microtile.
// Requirements: K % 16 == 0, N % 128 == 0.
#define BM 128
#define BN 128
#define BK 16
#define TM 8
#define TN 8

template <bool RELU_IN, bool RELU_OUT>
__global__ void __launch_bounds__(256)
sgemm_kernel(const float* __restrict__ A, const float* __restrict__ B,
             const float* __restrict__ bias, float* __restrict__ C,
             int M, int N, int K) {
    __shared__ float As[BK][BM + 4];
    __shared__ float Bs[BK][BN];
    const int tid = threadIdx.x;
    const int block_m = blockIdx.y * BM;
    const int block_n = blockIdx.x * BN;

    // A staging: 128 rows x 16 cols = 2048 floats = 512 float4; 2 iters.
    const int a_r  = tid >> 2;          // 0..63
    const int a_c4 = (tid & 3) * 4;     // 0,4,8,12
    // B staging: 16 rows x 128 cols = 2048 floats = 512 float4; 2 iters.
    const int b_r  = tid >> 5;          // 0..7
    const int b_c4 = (tid & 31) * 4;    // 0..124

    const int tx = tid & 15;            // N dir (8 cols each)
    const int ty = tid >> 4;            // M dir (8 rows each)

    float acc[TM][TN];
#pragma unroll
    for (int i = 0; i < TM; i++)
#pragma unroll
        for (int j = 0; j < TN; j++) acc[i][j] = 0.f;

    for (int k0 = 0; k0 < K; k0 += BK) {
#pragma unroll
        for (int rr = 0; rr < 2; rr++) {
            int row = block_m + a_r + rr * 64;
            float4 v = make_float4(0.f, 0.f, 0.f, 0.f);
            if (row < M) v = *(const float4*)(A + (size_t)row * K + k0 + a_c4);
            if (RELU_IN) {
                v.x = fmaxf(v.x, 0.f); v.y = fmaxf(v.y, 0.f);
                v.z = fmaxf(v.z, 0.f); v.w = fmaxf(v.w, 0.f);
            }
            As[a_c4 + 0][a_r + rr * 64] = v.x;
            As[a_c4 + 1][a_r + rr * 64] = v.y;
            As[a_c4 + 2][a_r + rr * 64] = v.z;
            As[a_c4 + 3][a_r + rr * 64] = v.w;
        }
#pragma unroll
        for (int rr = 0; rr < 2; rr++) {
            int r = b_r + rr * 8;
            float4 v = *(const float4*)(B + (size_t)(k0 + r) * N + block_n + b_c4);
            *(float4*)&Bs[r][b_c4] = v;
        }
        __syncthreads();
#pragma unroll
        for (int k = 0; k < BK; k++) {
            float a[TM], bf[TN];
            float4 a0 = *(float4*)&As[k][ty * TM];
            float4 a1 = *(float4*)&As[k][ty * TM + 4];
            a[0]=a0.x; a[1]=a0.y; a[2]=a0.z; a[3]=a0.w;
            a[4]=a1.x; a[5]=a1.y; a[6]=a1.z; a[7]=a1.w;
            float4 b0 = *(float4*)&Bs[k][tx * TN];
            float4 b1 = *(float4*)&Bs[k][tx * TN + 4];
            bf[0]=b0.x; bf[1]=b0.y; bf[2]=b0.z; bf[3]=b0.w;
            bf[4]=b1.x; bf[5]=b1.y; bf[6]=b1.z; bf[7]=b1.w;
#pragma unroll
            for (int i = 0; i < TM; i++)
#pragma unroll
                for (int j = 0; j < TN; j++) acc[i][j] += a[i] * bf[j];
        }
        __syncthreads();
    }

#pragma unroll
    for (int i = 0; i < TM; i++) {
        int row = block_m + ty * TM + i;
        if (row >= M) continue;
#pragma unroll
        for (int j = 0; j < TN; j++) {
            int col = block_n + tx * TN + j;
            float v = acc[i][j] + (bias ? bias[col] : 0.f);
            if (RELU_OUT) v = fmaxf(v, 0.f);
            C[(size_t)row * N + col] = v;
        }
    }
}

// ---------------- GAT attention-coefficient prep: al_s/al_d[n,h] = <h[n,h,:], a>
template <int D>
__global__ void alpha_prep_kernel(const float* __restrict__ h,
                                  const float* __restrict__ a_src,
                                  const float* __restrict__ a_dst,
                                  float* __restrict__ als, float* __restrict__ ald,
                                  int N) {
    int w = (blockIdx.x * blockDim.x + threadIdx.x) >> 5;
    int lane = threadIdx.x & 31;
    if (w >= N * HEADS) return;
    int n = w >> 1, hd = w & 1;
    const float* hr = h + (size_t)n * (HEADS * D) + hd * D;
    const float* as = a_src + hd * D;
    const float* ad = a_dst + hd * D;
    float ss = 0.f, dd = 0.f;
    for (int i = lane; i < D; i += 32) {
        float v = hr[i];
        ss += v * as[i];
        dd += v * ad[i];
    }
#pragma unroll
    for (int o = 16; o; o >>= 1) {
        ss += __shfl_xor_sync(0xffffffffu, ss, o);
        dd += __shfl_xor_sync(0xffffffffu, dd, o);
    }
    if (lane == 0) {
        als[n * HEADS + hd] = ss;
        ald[n * HEADS + hd] = dd;
    }
}

// ---------------- fused per-node GAT: softmax over in-edges + weighted agg + head-mean + bias
#define GCHUNK 64

template <int D>
__global__ void gat_node_kernel(const float* __restrict__ h,
                                const float* __restrict__ als,
                                const float* __restrict__ ald,
                                const float* __restrict__ bias,
                                const int* __restrict__ rowptr,
                                const int* __restrict__ srcs,
                                float* __restrict__ out) {
    constexpr int NW = D / 32;
    const int n = blockIdx.x;
    const int tid = threadIdx.x;     // blockDim == D
    const int beg = rowptr[n];
    const int deg = rowptr[n + 1] - beg;

    if (deg == 0) {
        out[(size_t)n * D + tid] = bias[tid];
        return;
    }

    __shared__ float rbuf[NW];
    __shared__ float bc;
    __shared__ int   src_sm[GCHUNK];
    __shared__ float a0_sm[GCHUNK];
    __shared__ float a1_sm[GCHUNK];

    const float ad0 = ald[n * 2 + 0];
    const float ad1 = ald[n * 2 + 1];

    auto edge_e = [&](int s, float& e0, float& e1) {
        e0 = als[s * 2 + 0] + ad0;
        e0 = (e0 > 0.f) ? e0 : 0.2f * e0;
        e1 = als[s * 2 + 1] + ad1;
        e1 = (e1 > 0.f) ? e1 : 0.2f * e1;
    };

    auto block_max = [&](float v) -> float {
#pragma unroll
        for (int o = 16; o; o >>= 1) v = fmaxf(v, __shfl_xor_sync(0xffffffffu, v, o));
        if ((tid & 31) == 0) rbuf[tid >> 5] = v;
        __syncthreads();
        if (tid == 0) {
            float r = rbuf[0];
#pragma unroll
            for (int i = 1; i < NW; i++) r = fmaxf(r, rbuf[i]);
            bc = r;
        }
        __syncthreads();
        float r = bc;
        __syncthreads();
        return r;
    };
    auto block_sum = [&](float v) -> float {
#pragma unroll
        for (int o = 16; o; o >>= 1) v += __shfl_xor_sync(0xffffffffu, v, o);
        if ((tid & 31) == 0) rbuf[tid >> 5] = v;
        __syncthreads();
        if (tid == 0) {
            float r = 0.f;
#pragma unroll
            for (int i = 0; i < NW; i++) r += rbuf[i];
            bc = r;
        }
        __syncthreads();
        float r = bc;
        __syncthreads();
        return r;
    };

    // phase A: per-head max
    float m0 = -CUDART_INF_F, m1 = -CUDART_INF_F;
    for (int j = tid; j < deg; j += D) {
        float e0, e1;
        edge_e(srcs[beg + j], e0, e1);
        m0 = fmaxf(m0, e0);
        m1 = fmaxf(m1, e1);
    }
    m0 = block_max(m0);
    m1 = block_max(m1);

    // phase B: per-head sum of exp
    float s0 = 0.f, s1 = 0.f;
    for (int j = tid; j < deg; j += D) {
        float e0, e1;
        edge_e(srcs[beg + j], e0, e1);
        s0 += __expf(e0 - m0);
        s1 += __expf(e1 - m1);
    }
    s0 = block_sum(s0);
    s1 = block_sum(s1);
    const float inv0 = 1.0f / (s0 + 1e-16f);
    const float inv1 = 1.0f / (s1 + 1e-16f);

    // phase C: chunked alpha + weighted accumulation
    float acc0 = 0.f, acc1 = 0.f;
    for (int base = 0; base < deg; base += GCHUNK) {
        int cnt = min(GCHUNK, deg - base);
        if (tid < cnt) {
            int s = srcs[beg + base + tid];
            float e0, e1;
            edge_e(s, e0, e1);
            src_sm[tid] = s;
            a0_sm[tid] = __expf(e0 - m0) * inv0;
            a1_sm[tid] = __expf(e1 - m1) * inv1;
        }
        __syncthreads();
#pragma unroll 2
        for (int j = 0; j < cnt; j++) {
            const float* hr = h + (size_t)src_sm[j] * (2 * D);
            acc0 += a0_sm[j] * hr[tid];
            acc1 += a1_sm[j] * hr[D + tid];
        }
        __syncthreads();
    }
    out[(size_t)n * D + tid] = 0.5f * (acc0 + acc1) + bias[tid];
}

// ---------------- launch ----------------
extern "C" void kernel_launch(void* const* d_in, const int* in_sizes, int n_in,
                              void* d_out, int out_size) {
    const float* states = (const float*)d_in[0];
    const int*   ei     = (const int*)d_in[1];
    const float* c1w = (const float*)d_in[2];
    const float* c1b = (const float*)d_in[3];
    const float* c2w = (const float*)d_in[4];
    const float* c2b = (const float*)d_in[5];
    const float* m1w = (const float*)d_in[6];
    const float* m1b = (const float*)d_in[7];
    const float* m2w = (const float*)d_in[8];
    const float* m2b = (const float*)d_in[9];
    const float* g1W  = (const float*)d_in[10];
    const float* g1as = (const float*)d_in[11];
    const float* g1ad = (const float*)d_in[12];
    const float* g1b  = (const float*)d_in[13];
    const float* g2W  = (const float*)d_in[14];
    const float* g2as = (const float*)d_in[15];
    const float* g2ad = (const float*)d_in[16];
    const float* g2b  = (const float*)d_in[17];
    float* out = (float*)d_out;

    const int Nn = in_sizes[0] / (C_IN * H_IN * H_IN);
    const int Ee = in_sizes[1] / 2;

    // device pointers for scratch
    float *p_pool1, *p_pool2, *p_feat1, *p_feat2, *p_h1, *p_h2, *p_out1, *p_als, *p_ald;
    int *p_cnt, *p_fill, *p_rowptr, *p_srcs;
    cudaGetSymbolAddress((void**)&p_pool1, g_pool1);
    cudaGetSymbolAddress((void**)&p_pool2, g_pool2);
    cudaGetSymbolAddress((void**)&p_feat1, g_feat1);
    cudaGetSymbolAddress((void**)&p_feat2, g_feat2);
    cudaGetSymbolAddress((void**)&p_h1, g_h1);
    cudaGetSymbolAddress((void**)&p_h2, g_h2);
    cudaGetSymbolAddress((void**)&p_out1, g_out1);
    cudaGetSymbolAddress((void**)&p_als, g_als);
    cudaGetSymbolAddress((void**)&p_ald, g_ald);
    cudaGetSymbolAddress((void**)&p_cnt, g_cnt);
    cudaGetSymbolAddress((void**)&p_fill, g_fill);
    cudaGetSymbolAddress((void**)&p_rowptr, g_rowptr);
    cudaGetSymbolAddress((void**)&p_srcs, g_srcs);

    cudaFuncSetAttribute(conv1_kernel, cudaFuncAttributeMaxDynamicSharedMemorySize,
                         C1_SMEM_FLOATS * (int)sizeof(float));

    // ---- CSR build (deterministic per launch) ----
    cudaMemsetAsync(p_cnt, 0, Nn * sizeof(int));
    cudaMemsetAsync(p_fill, 0, Nn * sizeof(int));
    hist_kernel<<<(Ee + 255) / 256, 256>>>(ei, p_cnt, Ee);
    scan_kernel<<<1, 1024>>>(p_cnt, p_rowptr, Nn, Ee);
    scatter_kernel<<<(Ee + 255) / 256, 256>>>(ei, p_rowptr, p_fill, p_srcs, Ee);

    // ---- CNN ----
    conv1_kernel<<<Nn, 512, C1_SMEM_FLOATS * sizeof(float)>>>(states, c1w, c1b, p_pool1);
    conv2_kernel<<<Nn, 256>>>(p_pool1, c2w, c2b, p_pool2);

    // ---- MLP ----
    dim3 gm1(MLP_HID / BN, (Nn + BM - 1) / BM);
    sgemm_kernel<false, true><<<gm1, 256>>>(p_pool2, m1w, m1b, p_feat1, Nn, MLP_HID, FLAT);
    dim3 gm2(MLP_OUT / BN, (Nn + BM - 1) / BM);
    sgemm_kernel<false, false><<<gm2, 256>>>(p_feat1, m2w, m2b, p_feat2, Nn, MLP_OUT, MLP_HID);

    // ---- GAT layer 1 ----
    dim3 gg1((HEADS * GNN_HID) / BN, (Nn + BM - 1) / BM);
    sgemm_kernel<false, false><<<gg1, 256>>>(p_feat2, g1W, nullptr, p_h1,
                                             Nn, HEADS * GNN_HID, MLP_OUT);
    alpha_prep_kernel<GNN_HID><<<(Nn * HEADS * 32 + 255) / 256, 256>>>(
        p_h1, g1as, g1ad, p_als, p_ald, Nn);
    gat_node_kernel<GNN_HID><<<Nn, GNN_HID>>>(p_h1, p_als, p_ald, g1b,
                                              p_rowptr, p_srcs, p_out1);

    // ---- GAT layer 2 (input relu fused into GEMM A-read) ----
    dim3 gg2((HEADS * EMB) / BN, (Nn + BM - 1) / BM);
    sgemm_kernel<true, false><<<gg2, 256>>>(p_out1, g2W, nullptr, p_h2,
                                            Nn, HEADS * EMB, GNN_HID);
    alpha_prep_kernel<EMB><<<(Nn * HEADS * 32 + 255) / 256, 256>>>(
        p_h2, g2as, g2ad, p_als, p_ald, Nn);
    gat_node_kernel<EMB><<<Nn, EMB>>>(p_h2, p_als, p_ald, g2b,
                                      p_rowptr, p_srcs, out);
}